// round 4
// baseline (speedup 1.0000x reference)
#include <cuda_runtime.h>
#include <cuda_bf16.h>
#include <cstdint>

#define NN 4096
#define HH 1024
#define VV 16384

#define BM 128
#define BN 128
#define BK 32
#define PAD 8
#define ASTR (BK + PAD)   // 40 bf16 = 80 bytes row stride (conflict-free for ldmatrix)

// Scratch: bf16 copies of input and weight, plus the loss accumulator.
__device__ __nv_bfloat16 g_A[(size_t)NN * HH];   // 8 MB
__device__ __nv_bfloat16 g_W[(size_t)VV * HH];   // 32 MB
__device__ double g_acc;

// ---------------------------------------------------------------------------
// fp32 -> bf16 conversion kernels (also zero the accumulator)
// ---------------------------------------------------------------------------
__global__ void cvtA_kernel(const float* __restrict__ src) {
    if (blockIdx.x == 0 && threadIdx.x == 0) g_acc = 0.0;
    size_t i = ((size_t)blockIdx.x * blockDim.x + threadIdx.x) * 4;
    float4 v = *(const float4*)(src + i);
    *(__nv_bfloat162*)(g_A + i)     = __floats2bfloat162_rn(v.x, v.y);
    *(__nv_bfloat162*)(g_A + i + 2) = __floats2bfloat162_rn(v.z, v.w);
}

__global__ void cvtW_kernel(const float* __restrict__ src) {
    size_t i = ((size_t)blockIdx.x * blockDim.x + threadIdx.x) * 4;
    float4 v = *(const float4*)(src + i);
    *(__nv_bfloat162*)(g_W + i)     = __floats2bfloat162_rn(v.x, v.y);
    *(__nv_bfloat162*)(g_W + i + 2) = __floats2bfloat162_rn(v.z, v.w);
}

// ---------------------------------------------------------------------------
// Fused GEMM + bias + squared-error reduction
// C tile 128x128, K-chunk 32, double-buffered cp.async, 8 warps (4m x 2n),
// warp tile 32x64 via mma.sync.m16n8k16 bf16.
// ---------------------------------------------------------------------------
__global__ __launch_bounds__(256, 2)
void gemm_mse_kernel(const float* __restrict__ target, const float* __restrict__ bias) {
    __shared__ __nv_bfloat16 As[2][BM][ASTR];
    __shared__ __nv_bfloat16 Bs[2][BN][ASTR];
    __shared__ float wsum[8];

    const int tid    = threadIdx.x;
    const int wid    = tid >> 5;
    const int lane   = tid & 31;
    const int warp_m = wid & 3;   // 0..3 -> m offset 32*warp_m
    const int warp_n = wid >> 2;  // 0..1 -> n offset 64*warp_n
    const int bm     = blockIdx.y;
    const int bn     = blockIdx.x;

    const __nv_bfloat16* Ag = g_A + (size_t)bm * BM * HH;
    const __nv_bfloat16* Wg = g_W + (size_t)bn * BN * HH;

    float acc[2][8][4];
#pragma unroll
    for (int i = 0; i < 2; i++)
#pragma unroll
        for (int j = 0; j < 8; j++)
#pragma unroll
            for (int k = 0; k < 4; k++) acc[i][j][k] = 0.f;

    // cp.async tile loader: 128 rows x 64B per operand -> 512 chunks of 16B each,
    // 2 chunks per thread per operand.
    auto load_tiles = [&](int buf, int k0) {
#pragma unroll
        for (int j = 0; j < 2; ++j) {
            int chunk = tid + j * 256;
            int r = chunk >> 2;
            int c = chunk & 3;
            const __nv_bfloat16* gp = Ag + (size_t)r * HH + k0 + c * 8;
            uint32_t sp = (uint32_t)__cvta_generic_to_shared(&As[buf][r][c * 8]);
            asm volatile("cp.async.cg.shared.global [%0], [%1], 16;\n" :: "r"(sp), "l"(gp));
            const __nv_bfloat16* gq = Wg + (size_t)r * HH + k0 + c * 8;
            uint32_t sq = (uint32_t)__cvta_generic_to_shared(&Bs[buf][r][c * 8]);
            asm volatile("cp.async.cg.shared.global [%0], [%1], 16;\n" :: "r"(sq), "l"(gq));
        }
        asm volatile("cp.async.commit_group;\n");
    };

    load_tiles(0, 0);
    const int KIT = HH / BK;  // 32
    for (int kt = 0; kt < KIT; ++kt) {
        const int cur = kt & 1;
        if (kt + 1 < KIT) {
            load_tiles(cur ^ 1, (kt + 1) * BK);
            asm volatile("cp.async.wait_group 1;\n");
        } else {
            asm volatile("cp.async.wait_group 0;\n");
        }
        __syncthreads();

#pragma unroll
        for (int ks = 0; ks < 2; ++ks) {
            // A fragments: 2 x (m16 k16)
            uint32_t a[2][4];
#pragma unroll
            for (int mt = 0; mt < 2; ++mt) {
                int row  = warp_m * 32 + mt * 16 + (lane & 15);
                int colb = ks * 32 + ((lane >> 4) << 4);
                uint32_t addr = (uint32_t)__cvta_generic_to_shared(&As[cur][row][0]) + colb;
                asm volatile("ldmatrix.sync.aligned.m8n8.x4.shared.b16 {%0,%1,%2,%3}, [%4];\n"
                             : "=r"(a[mt][0]), "=r"(a[mt][1]), "=r"(a[mt][2]), "=r"(a[mt][3])
                             : "r"(addr));
            }
            // B fragments: 8 x (k16 n8), loaded as 4 x ldmatrix.x4 (n16 each)
            uint32_t b[8][2];
#pragma unroll
            for (int ng = 0; ng < 4; ++ng) {
                int row  = warp_n * 64 + ng * 16 + (lane & 7) + (((lane >> 4) & 1) << 3);
                int colb = ks * 32 + (((lane >> 3) & 1) << 4);
                uint32_t addr = (uint32_t)__cvta_generic_to_shared(&Bs[cur][row][0]) + colb;
                asm volatile("ldmatrix.sync.aligned.m8n8.x4.shared.b16 {%0,%1,%2,%3}, [%4];\n"
                             : "=r"(b[2 * ng][0]), "=r"(b[2 * ng][1]),
                               "=r"(b[2 * ng + 1][0]), "=r"(b[2 * ng + 1][1])
                             : "r"(addr));
            }
#pragma unroll
            for (int mt = 0; mt < 2; ++mt)
#pragma unroll
                for (int nt = 0; nt < 8; ++nt) {
                    asm volatile(
                        "mma.sync.aligned.m16n8k16.row.col.f32.bf16.bf16.f32 "
                        "{%0,%1,%2,%3}, {%4,%5,%6,%7}, {%8,%9}, {%0,%1,%2,%3};\n"
                        : "+f"(acc[mt][nt][0]), "+f"(acc[mt][nt][1]),
                          "+f"(acc[mt][nt][2]), "+f"(acc[mt][nt][3])
                        : "r"(a[mt][0]), "r"(a[mt][1]), "r"(a[mt][2]), "r"(a[mt][3]),
                          "r"(b[nt][0]), "r"(b[nt][1]));
                }
        }
        __syncthreads();
    }

    // Fused epilogue: d = c + bias[v] - target[n,v]; accumulate d*d.
    float lsum = 0.f;
#pragma unroll
    for (int mt = 0; mt < 2; ++mt) {
        int r0 = bm * BM + warp_m * 32 + mt * 16 + (lane >> 2);
#pragma unroll
        for (int nt = 0; nt < 8; ++nt) {
            int v0 = bn * BN + warp_n * 64 + nt * 8 + ((lane & 3) << 1);
            float2 bb = *(const float2*)(bias + v0);
            float2 t0 = *(const float2*)(target + (size_t)r0 * VV + v0);
            float2 t1 = *(const float2*)(target + (size_t)(r0 + 8) * VV + v0);
            float d;
            d = acc[mt][nt][0] + bb.x - t0.x; lsum += d * d;
            d = acc[mt][nt][1] + bb.y - t0.y; lsum += d * d;
            d = acc[mt][nt][2] + bb.x - t1.x; lsum += d * d;
            d = acc[mt][nt][3] + bb.y - t1.y; lsum += d * d;
        }
    }
#pragma unroll
    for (int o = 16; o; o >>= 1) lsum += __shfl_xor_sync(0xffffffff, lsum, o);
    if (lane == 0) wsum[wid] = lsum;
    __syncthreads();
    if (wid == 0) {
        float s = (lane < 8) ? wsum[lane] : 0.f;
#pragma unroll
        for (int o = 4; o; o >>= 1) s += __shfl_xor_sync(0xffffffff, s, o);
        if (lane == 0) atomicAdd(&g_acc, (double)s);
    }
}

__global__ void final_kernel(float* out) {
    out[0] = (float)(g_acc / (double)((size_t)NN * VV));
}

// ---------------------------------------------------------------------------
extern "C" void kernel_launch(void* const* d_in, const int* in_sizes, int n_in,
                              void* d_out, int out_size) {
    const float* inp    = (const float*)d_in[0];  // (N, H)
    const float* wt     = (const float*)d_in[1];  // (V, H)
    const float* target = (const float*)d_in[2];  // (N, V)
    const float* bias   = (const float*)d_in[3];  // (V,)
    float* out = (float*)d_out;

    cvtA_kernel<<<(NN * HH) / 1024, 256>>>(inp);
    cvtW_kernel<<<(VV * HH) / 1024, 256>>>(wt);

    dim3 grid(VV / BN, NN / BM);  // (128, 32)
    gemm_mse_kernel<<<grid, 256>>>(target, bias);

    final_kernel<<<1, 1>>>(out);
}